// round 11
// baseline (speedup 1.0000x reference)
#include <cuda_runtime.h>
#include <cstdint>

#define BB 64
#define NN 512
#define HH 128
#define NCOG 72
#define NRB 72

__device__ __align__(16) float g_part[(size_t)BB * NN * HH]; // split-k partials (ks=1)
__device__ int      g_jlist[BB][NN];
__device__ int      g_jcnt[BB];
__device__ unsigned g_maxbits;

// ---------------------------------------------------------------------------
// Per batch: sorted active-index list (mask!=0); reset global max.
// ---------------------------------------------------------------------------
__global__ void k_compact(const float* __restrict__ mask) {
    int b = blockIdx.x;
    int j = threadIdx.x;
    if (b == 0 && j == 0) g_maxbits = 0u;

    bool act = (mask[b * NN + j] != 0.0f);
    unsigned ball = __ballot_sync(0xffffffffu, act);

    __shared__ int wcnt[16], wbase[16];
    int warp = j >> 5, lane = j & 31;
    if (lane == 0) wcnt[warp] = __popc(ball);
    __syncthreads();
    if (j == 0) {
        int s = 0;
        for (int w = 0; w < 16; w++) { wbase[w] = s; s += wcnt[w]; }
        g_jcnt[b] = s;
    }
    __syncthreads();
    if (act) {
        int pos = wbase[warp] + __popc(ball & ((1u << lane) - 1u));
        g_jlist[b][pos] = j;
    }
}

// ---------------------------------------------------------------------------
// FUSED kernel: computes W tiles on the fly (no g_wc round-trip) and does the
// compacted GEMM with UNNORMALIZED accumulation; tracks max via atomicMax.
// Block: 64 i x 128 h x half-K. 256 threads, per-thread 4i x 8h.
// blockIdx.x encodes (i-tile, ks). ks=0 -> out, ks=1 -> g_part.
// sWT transposed [kk][ii], stride 68: w read = single LDS.128 broadcast
// (5 smem wavefronts per warp-kk vs 32 FFMA -> FFMA-bound inner loop).
// ---------------------------------------------------------------------------
__global__ void __launch_bounds__(256, 3) k_fused(
    const int*   __restrict__ rmat,
    const float* __restrict__ dmat,
    const int*   __restrict__ cog,
    const float* __restrict__ domain,
    const float* __restrict__ h_t,
    float*       __restrict__ out)
{
    int b   = blockIdx.y;
    int cnt = g_jcnt[b];
    int bx  = blockIdx.x;
    int it  = bx >> 1;
    int ks  = bx & 1;
    int ip0 = it * 64;
    if (ip0 >= cnt) return;

    int nt   = (cnt + 31) >> 5;          // 32-wide k-tiles
    int half = (nt + 1) >> 1;
    int t0   = ks * half;
    int t1   = min(nt, t0 + half);
    if (t0 >= t1) return;

    int tid = threadIdx.x;
    int tx  = tid & 15;                  // h octet
    int ty  = tid >> 4;                  // i quad (0..15)

    __shared__ __align__(16) float sWT[32][68];   // [kk][ii], 272B rows (16B-aligned)
    __shared__ __align__(16) float sH[32][128];
    __shared__ int s_jl[NN];
    __shared__ int s_il[64];
    __shared__ float s_wm[8];

    #pragma unroll
    for (int q = 0; q < 2; q++) {
        int jc = tid + q * 256;
        s_jl[jc] = (jc < cnt) ? g_jlist[b][jc] : 0;
    }
    if (tid < 64) {
        int ip = ip0 + tid;
        s_il[tid] = (ip < cnt) ? g_jlist[b][ip] : 0;
    }

    float acc[4][8];
    #pragma unroll
    for (int a = 0; a < 4; a++)
        #pragma unroll
        for (int c = 0; c < 8; c++) acc[a][c] = 0.f;
    float wmax = 0.f;

    const float* hb = h_t + (size_t)b * HH;

    for (int kt = t0; kt < t1; kt++) {
        int kc0 = kt * 32;
        __syncthreads();    // previous tile consumed

        // W tile 64x32 computed on the fly. 2048 elems, 8/thread.
        // Warp-constant ii (coalesced row gather), kk = lane.
        #pragma unroll
        for (int rep = 0; rep < 8; rep++) {
            int e  = rep * 256 + tid;
            int ii = e >> 5;
            int kk = e & 31;
            float v = 0.f;
            if (ip0 + ii < cnt && kc0 + kk < cnt) {
                int i = s_il[ii];
                int j = s_jl[kc0 + kk];
                size_t src = ((size_t)(b * NN + i)) * NN + j;
                float dom = __ldg(domain + cog[src] * NRB + rmat[src]);
                v = fmaxf(dom - dmat[src], 0.f);
            }
            sWT[kk][ii] = v;
            wmax = fmaxf(wmax, v);
        }
        // H tile 32x128 gathered rows, float4 coalesced. 4/thread.
        #pragma unroll
        for (int rep = 0; rep < 4; rep++) {
            int e  = rep * 256 + tid;
            int kk = e >> 5;
            int h4 = e & 31;
            int j  = s_jl[kc0 + kk];
            float4 hv = *(const float4*)(hb + (size_t)j * (BB * HH) + h4 * 4);
            *(float4*)(&sH[kk][h4 * 4]) = hv;
        }
        __syncthreads();

        #pragma unroll
        for (int kk = 0; kk < 32; kk++) {
            float4 w4 = *(const float4*)(&sWT[kk][ty * 4]);   // 1 wf broadcast
            float4 h0 = *(const float4*)(&sH[kk][tx * 4]);
            float4 h1 = *(const float4*)(&sH[kk][64 + tx * 4]);
            acc[0][0] = fmaf(w4.x, h0.x, acc[0][0]);
            acc[0][1] = fmaf(w4.x, h0.y, acc[0][1]);
            acc[0][2] = fmaf(w4.x, h0.z, acc[0][2]);
            acc[0][3] = fmaf(w4.x, h0.w, acc[0][3]);
            acc[0][4] = fmaf(w4.x, h1.x, acc[0][4]);
            acc[0][5] = fmaf(w4.x, h1.y, acc[0][5]);
            acc[0][6] = fmaf(w4.x, h1.z, acc[0][6]);
            acc[0][7] = fmaf(w4.x, h1.w, acc[0][7]);
            acc[1][0] = fmaf(w4.y, h0.x, acc[1][0]);
            acc[1][1] = fmaf(w4.y, h0.y, acc[1][1]);
            acc[1][2] = fmaf(w4.y, h0.z, acc[1][2]);
            acc[1][3] = fmaf(w4.y, h0.w, acc[1][3]);
            acc[1][4] = fmaf(w4.y, h1.x, acc[1][4]);
            acc[1][5] = fmaf(w4.y, h1.y, acc[1][5]);
            acc[1][6] = fmaf(w4.y, h1.z, acc[1][6]);
            acc[1][7] = fmaf(w4.y, h1.w, acc[1][7]);
            acc[2][0] = fmaf(w4.z, h0.x, acc[2][0]);
            acc[2][1] = fmaf(w4.z, h0.y, acc[2][1]);
            acc[2][2] = fmaf(w4.z, h0.z, acc[2][2]);
            acc[2][3] = fmaf(w4.z, h0.w, acc[2][3]);
            acc[2][4] = fmaf(w4.z, h1.x, acc[2][4]);
            acc[2][5] = fmaf(w4.z, h1.y, acc[2][5]);
            acc[2][6] = fmaf(w4.z, h1.z, acc[2][6]);
            acc[2][7] = fmaf(w4.z, h1.w, acc[2][7]);
            acc[3][0] = fmaf(w4.w, h0.x, acc[3][0]);
            acc[3][1] = fmaf(w4.w, h0.y, acc[3][1]);
            acc[3][2] = fmaf(w4.w, h0.z, acc[3][2]);
            acc[3][3] = fmaf(w4.w, h0.w, acc[3][3]);
            acc[3][4] = fmaf(w4.w, h1.x, acc[3][4]);
            acc[3][5] = fmaf(w4.w, h1.y, acc[3][5]);
            acc[3][6] = fmaf(w4.w, h1.z, acc[3][6]);
            acc[3][7] = fmaf(w4.w, h1.w, acc[3][7]);
        }
    }

    // Block max -> global atomicMax (normalization applied in k_finalize).
    #pragma unroll
    for (int off = 16; off; off >>= 1)
        wmax = fmaxf(wmax, __shfl_xor_sync(0xffffffffu, wmax, off));
    if ((tid & 31) == 0) s_wm[tid >> 5] = wmax;
    __syncthreads();
    if (tid == 0) {
        float bm = s_wm[0];
        #pragma unroll
        for (int w = 1; w < 8; w++) bm = fmaxf(bm, s_wm[w]);
        atomicMax(&g_maxbits, __float_as_uint(bm));
    }

    // Unnormalized write (active rows only).
    float* dstb = ks ? g_part : out;
    #pragma unroll
    for (int a = 0; a < 4; a++) {
        int ipl = ty * 4 + a;
        if (ip0 + ipl < cnt) {
            int i = s_il[ipl];
            float* op = dstb + ((size_t)(b * NN + i)) * HH;
            *(float4*)(op + tx * 4)      = make_float4(acc[a][0], acc[a][1], acc[a][2], acc[a][3]);
            *(float4*)(op + 64 + tx * 4) = make_float4(acc[a][4], acc[a][5], acc[a][6], acc[a][7]);
        }
    }
}

// ---------------------------------------------------------------------------
// Finalize: out = active ? (out + (split? part : 0)) * (1/max) : 0.
// Also clears the 0xAA poison on inactive rows. Grid (NN/8, BB), 256 thr.
// ---------------------------------------------------------------------------
__global__ void __launch_bounds__(256) k_finalize(
    const float* __restrict__ mask,
    float*       __restrict__ out)
{
    int b  = blockIdx.y;
    int rr = threadIdx.x >> 5;
    int c  = threadIdx.x & 31;
    int i  = blockIdx.x * 8 + rr;

    float inv = 1.0f / __uint_as_float(g_maxbits);
    int cnt  = g_jcnt[b];
    int nt   = (cnt + 31) >> 5;
    int half = (nt + 1) >> 1;
    bool add = (half < nt);              // did ks=1 run?

    size_t off = ((size_t)(b * NN + i)) * HH;
    float4* po = (float4*)(out + off);
    float4 o = make_float4(0.f, 0.f, 0.f, 0.f);
    if (mask[b * NN + i] != 0.0f) {
        float4 a = po[c];
        if (add) {
            float4 p = ((const float4*)(g_part + off))[c];
            a.x += p.x; a.y += p.y; a.z += p.z; a.w += p.w;
        }
        o = make_float4(a.x * inv, a.y * inv, a.z * inv, a.w * inv);
    }
    po[c] = o;
}

// ---------------------------------------------------------------------------
extern "C" void kernel_launch(void* const* d_in, const int* in_sizes, int n_in,
                              void* d_out, int out_size)
{
    const float* h_t    = (const float*)d_in[0];
    const int*   r_mat  = (const int*)  d_in[1];
    const float* d_mat  = (const float*)d_in[2];
    const float* mask   = (const float*)d_in[3];
    const int*   cog    = (const int*)  d_in[4];
    const float* domain = (const float*)d_in[5];
    float* out = (float*)d_out;

    k_compact<<<BB, NN>>>(mask);
    dim3 g1((NN / 64) * 2, BB);          // (i-tile, ks) pairs
    k_fused<<<g1, 256>>>(r_mat, d_mat, cog, domain, h_t, out);
    dim3 g2(NN / 8, BB);
    k_finalize<<<g2, 256>>>(mask, out);
}

// round 12
// speedup vs baseline: 1.4714x; 1.4714x over previous
#include <cuda_runtime.h>
#include <cstdint>

#define BB 64
#define NN 512
#define HH 128
#define NCOG 72
#define NRB 72

__device__ __align__(16) float g_wc[(size_t)BB * NN * NN];   // compacted w rows (L2-resident: 17MB)
__device__ __align__(16) float g_part[(size_t)BB * NN * HH]; // split-k partials (ks=1)
__device__ int      g_jlist[BB][NN];
__device__ int      g_jcnt[BB];
__device__ unsigned g_maxbits;

// ---------------------------------------------------------------------------
__global__ void k_compact(const float* __restrict__ mask) {
    int b = blockIdx.x;
    int j = threadIdx.x;
    if (b == 0 && j == 0) g_maxbits = 0u;

    bool act = (mask[b * NN + j] != 0.0f);
    unsigned ball = __ballot_sync(0xffffffffu, act);

    __shared__ int wcnt[16], wbase[16];
    int warp = j >> 5, lane = j & 31;
    if (lane == 0) wcnt[warp] = __popc(ball);
    __syncthreads();
    if (j == 0) {
        int s = 0;
        for (int w = 0; w < 16; w++) { wbase[w] = s; s += wcnt[w]; }
        g_jcnt[b] = s;
    }
    __syncthreads();
    if (act) {
        int pos = wbase[warp] + __popc(ball & ((1u << lane) - 1u));
        g_jlist[b][pos] = j;
    }
}

// ---------------------------------------------------------------------------
// Build compacted w rows (R8 version: DENSE int4/float4 reads, smem scatter
// staging, compact float4 writes; 8 rows/block; s_pos built once).
// ---------------------------------------------------------------------------
__global__ void __launch_bounds__(128) k_build_w(
    const int*   __restrict__ rmat,
    const float* __restrict__ dmat,
    const int*   __restrict__ cog,
    const float* __restrict__ domain)
{
    int b   = blockIdx.y;
    int cnt = g_jcnt[b];
    int ip_base = blockIdx.x * 8;
    if (ip_base >= cnt) return;

    __shared__ int s_pos[NN];
    __shared__ __align__(16) float s_stage[NN];
    __shared__ int s_rows[8];
    __shared__ float smax[4];
    int t = threadIdx.x;

    #pragma unroll
    for (int q = 0; q < 4; q++) {
        s_pos[t + q * 128]   = -1;
        s_stage[t + q * 128] = 0.f;
    }
    __syncthreads();
    #pragma unroll
    for (int q = 0; q < 4; q++) {
        int jc = t + q * 128;
        if (jc < cnt) s_pos[g_jlist[b][jc]] = jc;
    }
    if (t < 8) {
        int ip = ip_base + t;
        s_rows[t] = (ip < cnt) ? g_jlist[b][ip] : -1;
    }
    __syncthreads();

    int cnt32 = (cnt + 31) & ~31;
    int nrows = min(8, cnt - ip_base);
    int j0 = t * 4;
    float lm = 0.f;

    for (int rr = 0; rr < nrows; rr++) {
        int i = s_rows[rr];
        size_t src = ((size_t)(b * NN + i)) * NN;

        int4   rv = *(const int4*)(rmat + src + j0);
        int4   cv = *(const int4*)(cog  + src + j0);
        float4 dv = *(const float4*)(dmat + src + j0);

        float w0 = fmaxf(__ldg(domain + cv.x * NRB + rv.x) - dv.x, 0.f);
        float w1 = fmaxf(__ldg(domain + cv.y * NRB + rv.y) - dv.y, 0.f);
        float w2 = fmaxf(__ldg(domain + cv.z * NRB + rv.z) - dv.z, 0.f);
        float w3 = fmaxf(__ldg(domain + cv.w * NRB + rv.w) - dv.w, 0.f);

        int p0 = s_pos[j0 + 0], p1 = s_pos[j0 + 1], p2 = s_pos[j0 + 2], p3 = s_pos[j0 + 3];
        if (p0 >= 0) { s_stage[p0] = w0; lm = fmaxf(lm, w0); }
        if (p1 >= 0) { s_stage[p1] = w1; lm = fmaxf(lm, w1); }
        if (p2 >= 0) { s_stage[p2] = w2; lm = fmaxf(lm, w2); }
        if (p3 >= 0) { s_stage[p3] = w3; lm = fmaxf(lm, w3); }
        __syncthreads();

        size_t dst = ((size_t)(b * NN + ip_base + rr)) * NN;
        if (j0 < cnt32)
            *(float4*)(g_wc + dst + j0) = *(const float4*)(s_stage + j0);
        __syncthreads();
    }

    #pragma unroll
    for (int off = 16; off; off >>= 1)
        lm = fmaxf(lm, __shfl_xor_sync(0xffffffffu, lm, off));
    if ((t & 31) == 0) smax[t >> 5] = lm;
    __syncthreads();
    if (t == 0) {
        float bm = fmaxf(fmaxf(smax[0], smax[1]), fmaxf(smax[2], smax[3]));
        atomicMax(&g_maxbits, __float_as_uint(bm));
    }
}

// ---------------------------------------------------------------------------
// Split-K compacted GEMM. Block: 64i x 128h x half-K, 256 threads,
// per-thread 4i x 8h. W read DENSE from g_wc (L2-resident), stored
// TRANSPOSED sWT[kk][ii] -> inner w read = single LDS.128 broadcast
// (5 smem wavefronts per warp-kk vs 16 FFMA-issue-cy -> FFMA-bound).
// blockIdx.x encodes (i-tile, ks). ks=0 -> out, ks=1 -> g_part (unnormalized).
// ---------------------------------------------------------------------------
__global__ void __launch_bounds__(256, 3) k_gemm(
    const float* __restrict__ h_t,
    float*       __restrict__ out)
{
    int b   = blockIdx.y;
    int cnt = g_jcnt[b];
    int bx  = blockIdx.x;
    int it  = bx >> 1;
    int ks  = bx & 1;
    int ip0 = it * 64;
    if (ip0 >= cnt) return;

    int nt   = (cnt + 31) >> 5;
    int half = (nt + 1) >> 1;
    int t0   = ks * half;
    int t1   = min(nt, t0 + half);
    if (t0 >= t1) return;

    int tid = threadIdx.x;
    int tx  = tid & 15;
    int ty  = tid >> 4;                  // 0..15

    __shared__ __align__(16) float sWT[32][68];   // [kk][ii], 272B rows (16B-aligned)
    __shared__ __align__(16) float sH[32][128];
    __shared__ int s_jl[NN];
    __shared__ int s_il[64];

    #pragma unroll
    for (int q = 0; q < 2; q++) {
        int jc = tid + q * 256;
        s_jl[jc] = (jc < cnt) ? g_jlist[b][jc] : 0;
    }
    if (tid < 64) {
        int ip = ip0 + tid;
        s_il[tid] = (ip < cnt) ? g_jlist[b][ip] : 0;
    }

    float acc[4][8];
    #pragma unroll
    for (int a = 0; a < 4; a++)
        #pragma unroll
        for (int c = 0; c < 8; c++) acc[a][c] = 0.f;

    const float* hb = h_t + (size_t)b * HH;
    const float* wb = g_wc + ((size_t)b * NN + ip0) * NN;

    for (int kt = t0; kt < t1; kt++) {
        int kc0 = kt * 32;
        __syncthreads();

        // W tile 64x32 dense from g_wc (L2): 512 float4, 2/thread, stored transposed.
        #pragma unroll
        for (int rep = 0; rep < 2; rep++) {
            int e  = rep * 256 + tid;
            int ii = e >> 3;
            int kq = e & 7;
            float4 v = make_float4(0.f, 0.f, 0.f, 0.f);
            if (ip0 + ii < cnt)
                v = *(const float4*)(wb + (size_t)ii * NN + kc0 + kq * 4);
            sWT[kq * 4 + 0][ii] = v.x;
            sWT[kq * 4 + 1][ii] = v.y;
            sWT[kq * 4 + 2][ii] = v.z;
            sWT[kq * 4 + 3][ii] = v.w;
        }
        // H tile 32x128 gathered rows: 1024 float4, 4/thread (512B-coalesced rows).
        #pragma unroll
        for (int rep = 0; rep < 4; rep++) {
            int e  = rep * 256 + tid;
            int kk = e >> 5;
            int h4 = e & 31;
            int j  = s_jl[kc0 + kk];
            float4 hv = *(const float4*)(hb + (size_t)j * (BB * HH) + h4 * 4);
            *(float4*)(&sH[kk][h4 * 4]) = hv;
        }
        __syncthreads();

        #pragma unroll
        for (int kk = 0; kk < 32; kk++) {
            float4 w4 = *(const float4*)(&sWT[kk][ty * 4]);   // 1 wavefront (2 addrs/warp)
            float4 h0 = *(const float4*)(&sH[kk][tx * 4]);
            float4 h1 = *(const float4*)(&sH[kk][64 + tx * 4]);
            acc[0][0] = fmaf(w4.x, h0.x, acc[0][0]);
            acc[0][1] = fmaf(w4.x, h0.y, acc[0][1]);
            acc[0][2] = fmaf(w4.x, h0.z, acc[0][2]);
            acc[0][3] = fmaf(w4.x, h0.w, acc[0][3]);
            acc[0][4] = fmaf(w4.x, h1.x, acc[0][4]);
            acc[0][5] = fmaf(w4.x, h1.y, acc[0][5]);
            acc[0][6] = fmaf(w4.x, h1.z, acc[0][6]);
            acc[0][7] = fmaf(w4.x, h1.w, acc[0][7]);
            acc[1][0] = fmaf(w4.y, h0.x, acc[1][0]);
            acc[1][1] = fmaf(w4.y, h0.y, acc[1][1]);
            acc[1][2] = fmaf(w4.y, h0.z, acc[1][2]);
            acc[1][3] = fmaf(w4.y, h0.w, acc[1][3]);
            acc[1][4] = fmaf(w4.y, h1.x, acc[1][4]);
            acc[1][5] = fmaf(w4.y, h1.y, acc[1][5]);
            acc[1][6] = fmaf(w4.y, h1.z, acc[1][6]);
            acc[1][7] = fmaf(w4.y, h1.w, acc[1][7]);
            acc[2][0] = fmaf(w4.z, h0.x, acc[2][0]);
            acc[2][1] = fmaf(w4.z, h0.y, acc[2][1]);
            acc[2][2] = fmaf(w4.z, h0.z, acc[2][2]);
            acc[2][3] = fmaf(w4.z, h0.w, acc[2][3]);
            acc[2][4] = fmaf(w4.z, h1.x, acc[2][4]);
            acc[2][5] = fmaf(w4.z, h1.y, acc[2][5]);
            acc[2][6] = fmaf(w4.z, h1.z, acc[2][6]);
            acc[2][7] = fmaf(w4.z, h1.w, acc[2][7]);
            acc[3][0] = fmaf(w4.w, h0.x, acc[3][0]);
            acc[3][1] = fmaf(w4.w, h0.y, acc[3][1]);
            acc[3][2] = fmaf(w4.w, h0.z, acc[3][2]);
            acc[3][3] = fmaf(w4.w, h0.w, acc[3][3]);
            acc[3][4] = fmaf(w4.w, h1.x, acc[3][4]);
            acc[3][5] = fmaf(w4.w, h1.y, acc[3][5]);
            acc[3][6] = fmaf(w4.w, h1.z, acc[3][6]);
            acc[3][7] = fmaf(w4.w, h1.w, acc[3][7]);
        }
    }

    // Unnormalized write (active rows only); finalize applies 1/max.
    float* dstb = ks ? g_part : out;
    #pragma unroll
    for (int a = 0; a < 4; a++) {
        int ipl = ty * 4 + a;
        if (ip0 + ipl < cnt) {
            int i = s_il[ipl];
            float* op = dstb + ((size_t)(b * NN + i)) * HH;
            *(float4*)(op + tx * 4)      = make_float4(acc[a][0], acc[a][1], acc[a][2], acc[a][3]);
            *(float4*)(op + 64 + tx * 4) = make_float4(acc[a][4], acc[a][5], acc[a][6], acc[a][7]);
        }
    }
}

// ---------------------------------------------------------------------------
// Finalize: out = active ? (out + (split? part : 0)) * (1/max) : 0.
// Clears 0xAA poison on inactive rows (zero_out kernel not needed).
// ---------------------------------------------------------------------------
__global__ void __launch_bounds__(256) k_finalize(
    const float* __restrict__ mask,
    float*       __restrict__ out)
{
    int b  = blockIdx.y;
    int rr = threadIdx.x >> 5;
    int c  = threadIdx.x & 31;
    int i  = blockIdx.x * 8 + rr;

    float inv = 1.0f / __uint_as_float(g_maxbits);
    int cnt  = g_jcnt[b];
    int nt   = (cnt + 31) >> 5;
    int half = (nt + 1) >> 1;
    bool add = (half < nt);

    size_t off = ((size_t)(b * NN + i)) * HH;
    float4* po = (float4*)(out + off);
    float4 o = make_float4(0.f, 0.f, 0.f, 0.f);
    if (mask[b * NN + i] != 0.0f) {
        float4 a = po[c];
        if (add) {
            float4 p = ((const float4*)(g_part + off))[c];
            a.x += p.x; a.y += p.y; a.z += p.z; a.w += p.w;
        }
        o = make_float4(a.x * inv, a.y * inv, a.z * inv, a.w * inv);
    }
    po[c] = o;
}

// ---------------------------------------------------------------------------
extern "C" void kernel_launch(void* const* d_in, const int* in_sizes, int n_in,
                              void* d_out, int out_size)
{
    const float* h_t    = (const float*)d_in[0];
    const int*   r_mat  = (const int*)  d_in[1];
    const float* d_mat  = (const float*)d_in[2];
    const float* mask   = (const float*)d_in[3];
    const int*   cog    = (const int*)  d_in[4];
    const float* domain = (const float*)d_in[5];
    float* out = (float*)d_out;

    k_compact<<<BB, NN>>>(mask);
    dim3 g1(NN / 8, BB);
    k_build_w<<<g1, 128>>>(r_mat, d_mat, cog, domain);
    dim3 g2((NN / 64) * 2, BB);          // (i-tile, ks) pairs
    k_gemm<<<g2, 256>>>(h_t, out);
    dim3 g3(NN / 8, BB);
    k_finalize<<<g3, 256>>>(mask, out);
}

// round 13
// speedup vs baseline: 1.5739x; 1.0697x over previous
#include <cuda_runtime.h>
#include <cstdint>

#define BB 64
#define NN 512
#define HH 128
#define NCOG 72
#define NRB 72

__device__ __align__(16) float g_wc[(size_t)BB * NN * NN];   // compacted w rows (~17MB, L2-resident)
__device__ int      g_jlist[BB][NN];
__device__ int      g_jcnt[BB];
__device__ unsigned g_maxbits;

// ---------------------------------------------------------------------------
__global__ void k_compact(const float* __restrict__ mask) {
    int b = blockIdx.x;
    int j = threadIdx.x;
    if (b == 0 && j == 0) g_maxbits = 0u;

    bool act = (mask[b * NN + j] != 0.0f);
    unsigned ball = __ballot_sync(0xffffffffu, act);

    __shared__ int wcnt[16], wbase[16];
    int warp = j >> 5, lane = j & 31;
    if (lane == 0) wcnt[warp] = __popc(ball);
    __syncthreads();
    if (j == 0) {
        int s = 0;
        for (int w = 0; w < 16; w++) { wbase[w] = s; s += wcnt[w]; }
        g_jcnt[b] = s;
    }
    __syncthreads();
    if (act) {
        int pos = wbase[warp] + __popc(ball & ((1u << lane) - 1u));
        g_jlist[b][pos] = j;
    }
}

// ---------------------------------------------------------------------------
// Zero inactive output rows (active rows are fully written by the GEMM).
// Grid (NN/8, BB), 256 thr = 8 rows x 32 float4.
// ---------------------------------------------------------------------------
__global__ void __launch_bounds__(256) k_zero_inactive(
    const float* __restrict__ mask,
    float*       __restrict__ out)
{
    int b  = blockIdx.y;
    int rr = threadIdx.x >> 5;
    int c  = threadIdx.x & 31;
    int i  = blockIdx.x * 8 + rr;
    if (mask[b * NN + i] != 0.0f) return;
    float4* po = (float4*)(out + ((size_t)(b * NN + i)) * HH);
    po[c] = make_float4(0.f, 0.f, 0.f, 0.f);
}

// ---------------------------------------------------------------------------
// Build compacted w rows (dense int4/float4 reads, smem scatter staging,
// compact float4 writes; 8 rows/block; s_pos built once). Folds global max.
// ---------------------------------------------------------------------------
__global__ void __launch_bounds__(128) k_build_w(
    const int*   __restrict__ rmat,
    const float* __restrict__ dmat,
    const int*   __restrict__ cog,
    const float* __restrict__ domain)
{
    int b   = blockIdx.y;
    int cnt = g_jcnt[b];
    int ip_base = blockIdx.x * 8;
    if (ip_base >= cnt) return;

    __shared__ int s_pos[NN];
    __shared__ __align__(16) float s_stage[NN];
    __shared__ int s_rows[8];
    __shared__ float smax[4];
    int t = threadIdx.x;

    #pragma unroll
    for (int q = 0; q < 4; q++) {
        s_pos[t + q * 128]   = -1;
        s_stage[t + q * 128] = 0.f;
    }
    __syncthreads();
    #pragma unroll
    for (int q = 0; q < 4; q++) {
        int jc = t + q * 128;
        if (jc < cnt) s_pos[g_jlist[b][jc]] = jc;
    }
    if (t < 8) {
        int ip = ip_base + t;
        s_rows[t] = (ip < cnt) ? g_jlist[b][ip] : -1;
    }
    __syncthreads();

    int cnt32 = (cnt + 31) & ~31;
    int nrows = min(8, cnt - ip_base);
    int j0 = t * 4;
    float lm = 0.f;

    for (int rr = 0; rr < nrows; rr++) {
        int i = s_rows[rr];
        size_t src = ((size_t)(b * NN + i)) * NN;

        int4   rv = *(const int4*)(rmat + src + j0);
        int4   cv = *(const int4*)(cog  + src + j0);
        float4 dv = *(const float4*)(dmat + src + j0);

        float w0 = fmaxf(__ldg(domain + cv.x * NRB + rv.x) - dv.x, 0.f);
        float w1 = fmaxf(__ldg(domain + cv.y * NRB + rv.y) - dv.y, 0.f);
        float w2 = fmaxf(__ldg(domain + cv.z * NRB + rv.z) - dv.z, 0.f);
        float w3 = fmaxf(__ldg(domain + cv.w * NRB + rv.w) - dv.w, 0.f);

        int p0 = s_pos[j0 + 0], p1 = s_pos[j0 + 1], p2 = s_pos[j0 + 2], p3 = s_pos[j0 + 3];
        if (p0 >= 0) { s_stage[p0] = w0; lm = fmaxf(lm, w0); }
        if (p1 >= 0) { s_stage[p1] = w1; lm = fmaxf(lm, w1); }
        if (p2 >= 0) { s_stage[p2] = w2; lm = fmaxf(lm, w2); }
        if (p3 >= 0) { s_stage[p3] = w3; lm = fmaxf(lm, w3); }
        __syncthreads();

        size_t dst = ((size_t)(b * NN + ip_base + rr)) * NN;
        if (j0 < cnt32)
            *(float4*)(g_wc + dst + j0) = *(const float4*)(s_stage + j0);
        __syncthreads();
    }

    #pragma unroll
    for (int off = 16; off; off >>= 1)
        lm = fmaxf(lm, __shfl_xor_sync(0xffffffffu, lm, off));
    if ((t & 31) == 0) smax[t >> 5] = lm;
    __syncthreads();
    if (t == 0) {
        float bm = fmaxf(fmaxf(smax[0], smax[1]), fmaxf(smax[2], smax[3]));
        atomicMax(&g_maxbits, __float_as_uint(bm));
    }
}

// ---------------------------------------------------------------------------
// H-split compacted GEMM. Block: 64i x 64h x FULL K, 256 threads,
// per-thread 4i x 4h. blockIdx.x encodes (i-tile, h-half) -> disjoint output,
// no reduction. 1/max applied in epilogue (max final before this launch).
// W stored transposed sWT[kk][ii]: inner w read = 1 LDS.128 broadcast.
// Per warp-kk: 3 smem wavefronts vs 16 FFMA -> FFMA-bound.
// ---------------------------------------------------------------------------
__global__ void __launch_bounds__(256, 4) k_gemm(
    const float* __restrict__ h_t,
    float*       __restrict__ out)
{
    int b   = blockIdx.y;
    int cnt = g_jcnt[b];
    int bx  = blockIdx.x;
    int it  = bx >> 1;
    int hs  = bx & 1;
    int ip0 = it * 64;
    if (ip0 >= cnt) return;
    int hoff = hs * 64;

    int nt = (cnt + 31) >> 5;

    int tid = threadIdx.x;
    int tx  = tid & 15;                  // h quad within 64
    int ty  = tid >> 4;                  // i quad (0..15)

    __shared__ __align__(16) float sWT[32][68];   // [kk][ii], 272B rows
    __shared__ __align__(16) float sH[32][64];
    __shared__ int s_jl[NN];
    __shared__ int s_il[64];

    #pragma unroll
    for (int q = 0; q < 2; q++) {
        int jc = tid + q * 256;
        s_jl[jc] = (jc < cnt) ? g_jlist[b][jc] : 0;
    }
    if (tid < 64) {
        int ip = ip0 + tid;
        s_il[tid] = (ip < cnt) ? g_jlist[b][ip] : 0;
    }

    float acc[4][4];
    #pragma unroll
    for (int a = 0; a < 4; a++)
        #pragma unroll
        for (int c = 0; c < 4; c++) acc[a][c] = 0.f;

    const float* hb = h_t + (size_t)b * HH + hoff;
    const float* wb = g_wc + ((size_t)b * NN + ip0) * NN;

    for (int kt = 0; kt < nt; kt++) {
        int kc0 = kt * 32;
        __syncthreads();

        // W tile 64x32 dense from g_wc: 512 float4, 2/thread, transposed store.
        #pragma unroll
        for (int rep = 0; rep < 2; rep++) {
            int e  = rep * 256 + tid;
            int ii = e >> 3;
            int kq = e & 7;
            float4 v = make_float4(0.f, 0.f, 0.f, 0.f);
            if (ip0 + ii < cnt)
                v = *(const float4*)(wb + (size_t)ii * NN + kc0 + kq * 4);
            sWT[kq * 4 + 0][ii] = v.x;
            sWT[kq * 4 + 1][ii] = v.y;
            sWT[kq * 4 + 2][ii] = v.z;
            sWT[kq * 4 + 3][ii] = v.w;
        }
        // H tile 32x64 gathered rows: 512 float4, 2/thread (256B-coalesced).
        #pragma unroll
        for (int rep = 0; rep < 2; rep++) {
            int e  = rep * 256 + tid;
            int kk = e >> 4;
            int h4 = e & 15;
            int j  = s_jl[kc0 + kk];
            float4 hv = *(const float4*)(hb + (size_t)j * (BB * HH) + h4 * 4);
            *(float4*)(&sH[kk][h4 * 4]) = hv;
        }
        __syncthreads();

        #pragma unroll
        for (int kk = 0; kk < 32; kk++) {
            float4 w4 = *(const float4*)(&sWT[kk][ty * 4]);   // broadcast, 1 wf
            float4 hv = *(const float4*)(&sH[kk][tx * 4]);    // 2 wf
            acc[0][0] = fmaf(w4.x, hv.x, acc[0][0]);
            acc[0][1] = fmaf(w4.x, hv.y, acc[0][1]);
            acc[0][2] = fmaf(w4.x, hv.z, acc[0][2]);
            acc[0][3] = fmaf(w4.x, hv.w, acc[0][3]);
            acc[1][0] = fmaf(w4.y, hv.x, acc[1][0]);
            acc[1][1] = fmaf(w4.y, hv.y, acc[1][1]);
            acc[1][2] = fmaf(w4.y, hv.z, acc[1][2]);
            acc[1][3] = fmaf(w4.y, hv.w, acc[1][3]);
            acc[2][0] = fmaf(w4.z, hv.x, acc[2][0]);
            acc[2][1] = fmaf(w4.z, hv.y, acc[2][1]);
            acc[2][2] = fmaf(w4.z, hv.z, acc[2][2]);
            acc[2][3] = fmaf(w4.z, hv.w, acc[2][3]);
            acc[3][0] = fmaf(w4.w, hv.x, acc[3][0]);
            acc[3][1] = fmaf(w4.w, hv.y, acc[3][1]);
            acc[3][2] = fmaf(w4.w, hv.z, acc[3][2]);
            acc[3][3] = fmaf(w4.w, hv.w, acc[3][3]);
        }
    }

    float inv = 1.0f / __uint_as_float(g_maxbits);
    #pragma unroll
    for (int a = 0; a < 4; a++) {
        int ipl = ty * 4 + a;
        if (ip0 + ipl < cnt) {
            int i = s_il[ipl];
            float* op = out + ((size_t)(b * NN + i)) * HH + hoff;
            *(float4*)(op + tx * 4) = make_float4(acc[a][0] * inv, acc[a][1] * inv,
                                                  acc[a][2] * inv, acc[a][3] * inv);
        }
    }
}

// ---------------------------------------------------------------------------
extern "C" void kernel_launch(void* const* d_in, const int* in_sizes, int n_in,
                              void* d_out, int out_size)
{
    const float* h_t    = (const float*)d_in[0];
    const int*   r_mat  = (const int*)  d_in[1];
    const float* d_mat  = (const float*)d_in[2];
    const float* mask   = (const float*)d_in[3];
    const int*   cog    = (const int*)  d_in[4];
    const float* domain = (const float*)d_in[5];
    float* out = (float*)d_out;

    k_compact<<<BB, NN>>>(mask);
    dim3 gz(NN / 8, BB);
    k_zero_inactive<<<gz, 256>>>(mask, out);
    dim3 g1(NN / 8, BB);
    k_build_w<<<g1, 128>>>(r_mat, d_mat, cog, domain);
    dim3 g2((NN / 64) * 2, BB);          // (i-tile, h-half) pairs
    k_gemm<<<g2, 256>>>(h_t, out);
}